// round 6
// baseline (speedup 1.0000x reference)
#include <cuda_runtime.h>
#include <cuda_bf16.h>
#include <cstdint>
#include <math.h>

#define KDIM 256
#define CDIM 128
#define P1_BLOCKS 148

__device__ float g_part[P1_BLOCKS * KDIM * CDIM];   // phase1 partials (fp32)
__device__ float g_xsB[KDIM * CDIM];                // spectrum, B-fragment layout (tf32 bits)

// ---------------- helpers (sm_80-level PTX only) ----------------
__device__ __forceinline__ uint32_t tf32r(float x) {
    uint32_t u; asm("cvt.rna.tf32.f32 %0, %1;" : "=r"(u) : "f"(x)); return u;
}
__device__ __forceinline__ void mma8(float* d, const uint32_t* a, const uint32_t* b) {
    asm volatile(
        "mma.sync.aligned.m16n8k8.row.col.f32.tf32.tf32.f32 "
        "{%0,%1,%2,%3}, {%4,%5,%6,%7}, {%8,%9}, {%0,%1,%2,%3};"
        : "+f"(d[0]), "+f"(d[1]), "+f"(d[2]), "+f"(d[3])
        : "r"(a[0]), "r"(a[1]), "r"(a[2]), "r"(a[3]), "r"(b[0]), "r"(b[1]));
}
__device__ __forceinline__ uint32_t smem_u32(const void* p) {
    uint32_t a;
    asm("{ .reg .u64 t; cvta.to.shared.u64 t, %1; cvt.u32.u64 %0, t; }" : "=r"(a) : "l"(p));
    return a;
}
__device__ __forceinline__ void cpa16(uint32_t dst, const void* src, int sz) {
    asm volatile("cp.async.ca.shared.global [%0], [%1], 16, %2;"
                 :: "r"(dst), "l"(src), "r"(sz) : "memory");
}
#define CP_COMMIT() asm volatile("cp.async.commit_group;" ::: "memory")
#define CP_WAIT0()  asm volatile("cp.async.wait_group 0;" ::: "memory")

// Fragment maps (m16n8k8 tf32, verified in R5):
//  A: reg q, lane l -> mL = (l>>2)+8*(q&1), kL = (l&3)+4*(q>>1)
//  B: reg q, lane l -> nL = l>>2,           kL = (l&3)+4*q
//  D: c0,c1 -> row=l/4, col=2*(l%4)+{0,1}; c2,c3 -> row+8

// ---- Phase1 raw-tile geometry (64-node chunks) ----
// A raw: [64 nodes][264]  (stride 264 = 256+8 -> bank = 8*(l&3)+(l>>2), conflict-free)
// B raw: [64 nodes][136]  (stride 136 = 128+8)
#define P1_AS   264
#define P1_ATU  (64 * P1_AS)     // 16896 u32
#define P1_BS   136
#define P1_BTU  (64 * P1_BS)     // 8704 u32
#define P1_STG  (P1_ATU + P1_BTU)            // 25600 u32 per stage
#define P1_SMEM (2 * P1_STG * 4)             // 204800 B

// ---- Phase2 geometry ----
// Bfull (frag layout): 32768 u32. A raw per kc: [128 rows][68] (stride 68 = 64+4)
#define P2_AS   68
#define P2_ATU  (128 * P2_AS)    // 8704 u32
#define P2_SMEM ((32768 + 2 * P2_ATU) * 4)   // 200704 B

// =====================================================================
// Phase 1: partial[b] = evecs^T @ x over node range. 512 thr = 16 warps
// (4m x 4n), warp tile 64x32, 64-node chunks, cp.async 2-stage ring.
// =====================================================================
__global__ void __launch_bounds__(512, 1)
phase1_kernel(const float* __restrict__ E, const float* __restrict__ X,
              int N, int chunk)
{
    extern __shared__ float smf[];
    const uint32_t sbase = smem_u32(smf);

    const int tid = threadIdx.x;
    const int warp = tid >> 5, lane = tid & 31;
    const int wm = warp >> 2;        // 0..3 -> m0 = wm*64 (eigen)
    const int wn = warp & 3;         // 0..3 -> n0 = wn*32 (chan)

    const int nb = blockIdx.x * chunk;
    const int ne = min(N, nb + chunk);
    const int niter = (ne - nb + 63) >> 6;

    float d[4][4][4];
    #pragma unroll
    for (int i = 0; i < 4; i++)
        #pragma unroll
        for (int j = 0; j < 4; j++)
            #pragma unroll
            for (int q = 0; q < 4; q++) d[i][j][q] = 0.f;

    // async copy of one 64-node chunk into stage st
    auto copy_chunk = [&](int s0, int st) {
        const uint32_t ab = sbase + (uint32_t)(st * P1_STG) * 4;
        const uint32_t bb = ab + P1_ATU * 4;
        #pragma unroll
        for (int t = 0; t < 8; t++) {
            int idx = tid + t * 512;          // 0..4095
            int r = idx >> 6, j = idx & 63;
            int node = s0 + r;
            int sz = (node < ne) ? 16 : 0;
            int nc = node < N ? node : N - 1;
            cpa16(ab + (uint32_t)(r * (P1_AS * 4)) + (uint32_t)(j * 16),
                  E + (size_t)nc * KDIM + j * 4, sz);
        }
        #pragma unroll
        for (int t = 0; t < 4; t++) {
            int idx = tid + t * 512;          // 0..2047
            int r = idx >> 5, j = idx & 31;
            int node = s0 + r;
            int sz = (node < ne) ? 16 : 0;
            int nc = node < N ? node : N - 1;
            cpa16(bb + (uint32_t)(r * (P1_BS * 4)) + (uint32_t)(j * 16),
                  X + (size_t)nc * CDIM + j * 4, sz);
        }
    };

    copy_chunk(nb, 0);
    CP_COMMIT();

    const int laA = (lane & 3) * P1_AS + (lane >> 2);
    const int laB = (lane & 3) * P1_BS + (lane >> 2);

    for (int it = 0; it < niter; it++) {
        CP_WAIT0();
        __syncthreads();
        if (it + 1 < niter) copy_chunk(nb + (it + 1) * 64, (it + 1) & 1);
        CP_COMMIT();

        const float* A0 = smf + (it & 1) * P1_STG;
        const float* B0 = A0 + P1_ATU;

        #pragma unroll
        for (int k8 = 0; k8 < 8; k8++) {
            uint32_t a[4][4], b[4][2];
            #pragma unroll
            for (int i = 0; i < 4; i++) {
                const int mb = wm * 64 + i * 16;
                const int base = laA + k8 * (8 * P1_AS) + mb;
                a[i][0] = tf32r(A0[base]);
                a[i][1] = tf32r(A0[base + 8]);
                a[i][2] = tf32r(A0[base + 4 * P1_AS]);
                a[i][3] = tf32r(A0[base + 4 * P1_AS + 8]);
            }
            #pragma unroll
            for (int j = 0; j < 4; j++) {
                const int nb2 = (wn * 4 + j) * 8;
                const int base = laB + k8 * (8 * P1_BS) + nb2;
                b[j][0] = tf32r(B0[base]);
                b[j][1] = tf32r(B0[base + 4 * P1_BS]);
            }
            #pragma unroll
            for (int i = 0; i < 4; i++)
                #pragma unroll
                for (int j = 0; j < 4; j++)
                    mma8(d[i][j], a[i], b[j]);
        }
        __syncthreads();
    }

    float* base = g_part + (size_t)blockIdx.x * (KDIM * CDIM);
    const int rql = lane >> 2, cql = (lane & 3) * 2;
    #pragma unroll
    for (int i = 0; i < 4; i++) {
        int row = wm * 64 + i * 16 + rql;
        #pragma unroll
        for (int j = 0; j < 4; j++) {
            int col = wn * 32 + j * 8 + cql;
            *(float2*)(base + row * CDIM + col)       = make_float2(d[i][j][0], d[i][j][1]);
            *(float2*)(base + (row + 8) * CDIM + col) = make_float2(d[i][j][2], d[i][j][3]);
        }
    }
}

// =====================================================================
// Reduce: xs[k][c] = exp(-evals[k]*t) * sum_b part[b][k][c]
// Output in B-fragment layout (tf32 bits).
// =====================================================================
__global__ void reduce_kernel(const float* __restrict__ evals,
                              const float* __restrict__ dt)
{
    int idx = blockIdx.x * 256 + threadIdx.x;   // k*128 + c
    float s0 = 0.f, s1 = 0.f, s2 = 0.f, s3 = 0.f;
    int b = 0;
    for (; b + 4 <= P1_BLOCKS; b += 4) {
        s0 += g_part[(size_t)(b + 0) * (KDIM * CDIM) + idx];
        s1 += g_part[(size_t)(b + 1) * (KDIM * CDIM) + idx];
        s2 += g_part[(size_t)(b + 2) * (KDIM * CDIM) + idx];
        s3 += g_part[(size_t)(b + 3) * (KDIM * CDIM) + idx];
    }
    for (; b < P1_BLOCKS; b++) s0 += g_part[(size_t)b * (KDIM * CDIM) + idx];
    float s = (s0 + s1) + (s2 + s3);

    int k = idx >> 7, c = idx & 127;
    float t = fmaxf(dt[0], 1e-8f);
    float v = expf(-evals[k] * t) * s;

    int k8 = k >> 3, kL = k & 7, ct = c >> 3, cL = c & 7;
    uint32_t addr = (uint32_t)(((k8 * 16 + ct) * 32 + cL * 4 + (kL & 3)) * 2 + (kL >> 2));
    g_xsB[addr] = __uint_as_float(tf32r(v));
}

// =====================================================================
// Phase 2: out[m,c] = sum_k E[m,k]*xs[k,c]. 256 thr = 8 warps (2m x 4n),
// M-tile 128, Bfull resident, raw-A cp.async 2-stage over 4 K-chunks.
// =====================================================================
__global__ void __launch_bounds__(256, 1)
phase2_kernel(const float* __restrict__ E, float* __restrict__ out, int N)
{
    extern __shared__ float smf[];
    uint32_t* Bfull = (uint32_t*)smf;               // 32768 u32 (frag layout)
    float* Araw = smf + 32768;                      // 2 x P2_ATU
    const uint32_t sbase = smem_u32(smf);

    const int tid = threadIdx.x;
    const int warp = tid >> 5, lane = tid & 31;
    const int wm = warp >> 2;        // 0..1
    const int wn = warp & 3;         // 0..3
    const int m0 = blockIdx.x * 128;

    auto copy_A = [&](int kc, int st) {
        const uint32_t ab = sbase + (uint32_t)(32768 + st * P2_ATU) * 4;
        #pragma unroll
        for (int t = 0; t < 8; t++) {
            int idx = tid + t * 256;          // 0..2047
            int r = idx >> 4, j = idx & 15;
            int node = m0 + r; if (node >= N) node = N - 1;
            cpa16(ab + (uint32_t)(r * (P2_AS * 4)) + (uint32_t)(j * 16),
                  E + (size_t)node * KDIM + kc * 64 + j * 4, 16);
        }
    };

    // preload Bfull + A kc0
    #pragma unroll
    for (int t = 0; t < 32; t++) {
        int idx = tid + t * 256;              // 0..8191 (16B units)
        cpa16(sbase + (uint32_t)(idx * 16), (const uint32_t*)g_xsB + idx * 4, 16);
    }
    copy_A(0, 0);
    CP_COMMIT();

    float d[4][4][4];
    #pragma unroll
    for (int i = 0; i < 4; i++)
        #pragma unroll
        for (int j = 0; j < 4; j++)
            #pragma unroll
            for (int q = 0; q < 4; q++) d[i][j][q] = 0.f;

    const int la2 = (lane >> 2) * P2_AS + (lane & 3);

    for (int kc = 0; kc < 4; kc++) {
        CP_WAIT0();
        __syncthreads();
        if (kc < 3) copy_A(kc + 1, (kc + 1) & 1);
        CP_COMMIT();

        const float* A0 = Araw + (kc & 1) * P2_ATU;

        #pragma unroll
        for (int k8l = 0; k8l < 8; k8l++) {
            const int k8g = kc * 8 + k8l;
            uint32_t a[4][4], b[4][2];
            #pragma unroll
            for (int i = 0; i < 4; i++) {
                const int base = la2 + (wm * 64 + i * 16) * P2_AS + k8l * 8;
                a[i][0] = tf32r(A0[base]);
                a[i][1] = tf32r(A0[base + 8 * P2_AS]);
                a[i][2] = tf32r(A0[base + 4]);
                a[i][3] = tf32r(A0[base + 8 * P2_AS + 4]);
            }
            #pragma unroll
            for (int j = 0; j < 4; j++) {
                uint2 bv = *(const uint2*)(Bfull + ((k8g * 16 + wn * 4 + j) * 32 + lane) * 2);
                b[j][0] = bv.x; b[j][1] = bv.y;
            }
            #pragma unroll
            for (int i = 0; i < 4; i++)
                #pragma unroll
                for (int j = 0; j < 4; j++)
                    mma8(d[i][j], a[i], b[j]);
        }
        __syncthreads();
    }

    const int rql = lane >> 2, cql = (lane & 3) * 2;
    #pragma unroll
    for (int i = 0; i < 4; i++) {
        int row = m0 + wm * 64 + i * 16 + rql;
        #pragma unroll
        for (int j = 0; j < 4; j++) {
            int col = wn * 32 + j * 8 + cql;
            if (row < N)
                *(float2*)(out + (size_t)row * CDIM + col) = make_float2(d[i][j][0], d[i][j][1]);
            if (row + 8 < N)
                *(float2*)(out + (size_t)(row + 8) * CDIM + col) = make_float2(d[i][j][2], d[i][j][3]);
        }
    }
}

// =====================================================================
extern "C" void kernel_launch(void* const* d_in, const int* in_sizes, int n_in,
                              void* d_out, int out_size)
{
    const float* evals = nullptr;
    const float* dt = nullptr;
    long big_a = -1, big_b = -1; int ia = -1, ib = -1;
    for (int i = 0; i < n_in; i++) {
        long sz = in_sizes[i];
        if (sz == 1)         dt = (const float*)d_in[i];
        else if (sz == KDIM) evals = (const float*)d_in[i];
        else {
            if (sz > big_a) { big_b = big_a; ib = ia; big_a = sz; ia = i; }
            else if (sz > big_b) { big_b = sz; ib = i; }
        }
    }
    const float* evecs = (const float*)d_in[ia];   // N*K (largest)
    const float* x     = (const float*)d_in[ib];   // N*C
    const int N = (int)(big_b / CDIM);

    static int cfg = 0;
    if (!cfg) {
        cudaFuncSetAttribute(phase1_kernel, cudaFuncAttributeMaxDynamicSharedMemorySize, P1_SMEM);
        cudaFuncSetAttribute(phase2_kernel, cudaFuncAttributeMaxDynamicSharedMemorySize, P2_SMEM);
        cfg = 1;
    }

    const int chunk = (N + P1_BLOCKS - 1) / P1_BLOCKS;
    phase1_kernel<<<P1_BLOCKS, 512, P1_SMEM>>>(evecs, x, N, chunk);
    reduce_kernel<<<(KDIM * CDIM) / 256, 256>>>(evals, dt);
    phase2_kernel<<<(N + 127) / 128, 256, P2_SMEM>>>(evecs, (float*)d_out, N);
}

// round 7
// speedup vs baseline: 1.2151x; 1.2151x over previous
#include <cuda_runtime.h>
#include <cuda_bf16.h>
#include <cstdint>
#include <math.h>

#define KDIM 256
#define CDIM 128
#define P1_BLOCKS 148

__device__ float g_part[P1_BLOCKS * KDIM * CDIM];   // phase1 partials (fp32)
__device__ float g_xsB[KDIM * CDIM];                // spectrum, B-fragment layout (tf32 bits)

// ---------------- helpers (sm_80-level PTX only) ----------------
__device__ __forceinline__ uint32_t tf32r(float x) {
    uint32_t u; asm("cvt.rna.tf32.f32 %0, %1;" : "=r"(u) : "f"(x)); return u;
}
__device__ __forceinline__ void mma8(float* d, const uint32_t* a, const uint32_t* b) {
    asm volatile(
        "mma.sync.aligned.m16n8k8.row.col.f32.tf32.tf32.f32 "
        "{%0,%1,%2,%3}, {%4,%5,%6,%7}, {%8,%9}, {%0,%1,%2,%3};"
        : "+f"(d[0]), "+f"(d[1]), "+f"(d[2]), "+f"(d[3])
        : "r"(a[0]), "r"(a[1]), "r"(a[2]), "r"(a[3]), "r"(b[0]), "r"(b[1]));
}
__device__ __forceinline__ uint32_t smem_u32(const void* p) {
    uint32_t a;
    asm("{ .reg .u64 t; cvta.to.shared.u64 t, %1; cvt.u32.u64 %0, t; }" : "=r"(a) : "l"(p));
    return a;
}
__device__ __forceinline__ void cpa16(uint32_t dst, const void* src) {
    asm volatile("cp.async.ca.shared.global [%0], [%1], 16;"
                 :: "r"(dst), "l"(src) : "memory");
}
#define CP_COMMIT() asm volatile("cp.async.commit_group;" ::: "memory")
#define CP_WAIT0()  asm volatile("cp.async.wait_group 0;" ::: "memory")

// Fragment maps (m16n8k8 tf32):
//  A: reg q, lane l -> mL = (l>>2)+8*(q&1), kL = (l&3)+4*(q>>1)
//  B: reg q, lane l -> nL = l>>2,           kL = (l&3)+4*q
//  D: c0,c1 -> row=l/4, col=2*(l%4)+{0,1}; c2,c3 -> row+8

// ---- Phase1 fragment-buffer strides (R5, proven) ----
#define P1_AMT  132
#define P1_AK8  (16 * P1_AMT)
#define P1_ABUF (4 * P1_AK8)
#define P1_BCT  66
#define P1_BK8  (16 * P1_BCT)
#define P1_BBUF (4 * P1_BK8)
#define P1_SMEM ((2 * P1_ABUF + 2 * P1_BBUF) * 4)   // 101376 B

// ---- Phase2 geometry: 32-k chunks, 8 chunks ----
#define P2_BST   4096                   // B frag chunk (u32)
#define P2_ARAW  8192                   // Araw offset (u32): [128 m][36]
#define P2_ARS   36
#define P2_AFRG  (P2_ARAW + 128 * P2_ARS)   // 12800
#define P2_TOT   (P2_AFRG + 4096)           // 16896 u32
#define P2_SMEM  (P2_TOT * 4)               // 67584 B -> 2+ CTAs/SM

// =====================================================================
// Phase 1 (R5, proven): partial[b] = evecs^T @ x. 512 thr, 16 warps
// (4m x 4n), 32-node chunks, reg staging + frag scatter + LDS.128 MMA.
// =====================================================================
__global__ void __launch_bounds__(512, 1)
phase1_kernel(const float* __restrict__ E, const float* __restrict__ X,
              int N, int chunk)
{
    extern __shared__ uint32_t sm[];
    uint32_t* Af = sm;
    uint32_t* Bf = sm + 2 * P1_ABUF;

    const int tid = threadIdx.x;
    const int warp = tid >> 5, lane = tid & 31;
    const int wm = warp >> 2;
    const int wn = warp & 3;

    float d[4][4][4];
    #pragma unroll
    for (int i = 0; i < 4; i++)
        #pragma unroll
        for (int j = 0; j < 4; j++)
            #pragma unroll
            for (int q = 0; q < 4; q++) d[i][j][q] = 0.f;

    const int nb = blockIdx.x * chunk;
    const int ne = min(N, nb + chunk);
    const int niter = (ne - nb + 31) >> 5;

    float4 curA[4], curB[2];

    auto loadc = [&](int s0, float4* A4, float4* B2) {
        #pragma unroll
        for (int it = 0; it < 4; it++) {
            int fid = tid + it * 512;
            int r = fid >> 6, j = fid & 63;
            int node = s0 + r;
            A4[it] = (node < ne) ? *(const float4*)(E + (size_t)node * KDIM + 4 * j)
                                 : make_float4(0.f, 0.f, 0.f, 0.f);
        }
        #pragma unroll
        for (int it = 0; it < 2; it++) {
            int fid = tid + it * 512;
            int r = fid >> 5, j = fid & 31;
            int node = s0 + r;
            B2[it] = (node < ne) ? *(const float4*)(X + (size_t)node * CDIM + 4 * j)
                                 : make_float4(0.f, 0.f, 0.f, 0.f);
        }
    };

    loadc(nb, curA, curB);

    for (int itn = 0; itn < niter; itn++) {
        const int buf = itn & 1;
        float4 nxtA[4], nxtB[2];
        if (itn + 1 < niter) loadc(nb + (itn + 1) * 32, nxtA, nxtB);

        uint32_t* Ab = Af + buf * P1_ABUF;
        uint32_t* Bb = Bf + buf * P1_BBUF;

        #pragma unroll
        for (int it = 0; it < 4; it++) {
            int fid = tid + it * 512;
            int r = fid >> 6, j = fid & 63;
            int k8 = r >> 3, kL = r & 7, mt = j >> 2;
            uint32_t base = (uint32_t)(k8 * P1_AK8 + mt * P1_AMT)
                          + ((j >> 1) & 1) + 2 * (kL >> 2);
            const float* v = (const float*)&curA[it];
            #pragma unroll
            for (int q = 0; q < 4; q++)
                Ab[base + (uint32_t)(16 * (j & 1) + 4 * q + (kL & 3)) * 4] = tf32r(v[q]);
        }
        #pragma unroll
        for (int it = 0; it < 2; it++) {
            int fid = tid + it * 512;
            int r = fid >> 5, j = fid & 31;
            int k8 = r >> 3, kL = r & 7, ct = j >> 1;
            uint32_t base = (uint32_t)(k8 * P1_BK8 + ct * P1_BCT) + (kL >> 2);
            const float* v = (const float*)&curB[it];
            #pragma unroll
            for (int q = 0; q < 4; q++)
                Bb[base + (uint32_t)(16 * (j & 1) + 4 * q + (kL & 3)) * 2] = tf32r(v[q]);
        }
        __syncthreads();

        #pragma unroll
        for (int k8 = 0; k8 < 4; k8++) {
            uint32_t a[4][4], b[4][2];
            #pragma unroll
            for (int i = 0; i < 4; i++) {
                uint4 av = *(const uint4*)(Ab + k8 * P1_AK8 + (wm * 4 + i) * P1_AMT + lane * 4);
                a[i][0] = av.x; a[i][1] = av.y; a[i][2] = av.z; a[i][3] = av.w;
            }
            #pragma unroll
            for (int j = 0; j < 4; j++) {
                uint2 bv = *(const uint2*)(Bb + k8 * P1_BK8 + (wn * 4 + j) * P1_BCT + lane * 2);
                b[j][0] = bv.x; b[j][1] = bv.y;
            }
            #pragma unroll
            for (int i = 0; i < 4; i++)
                #pragma unroll
                for (int j = 0; j < 4; j++)
                    mma8(d[i][j], a[i], b[j]);
        }
        __syncthreads();

        #pragma unroll
        for (int it = 0; it < 4; it++) curA[it] = nxtA[it];
        curB[0] = nxtB[0]; curB[1] = nxtB[1];
    }

    float* base = g_part + (size_t)blockIdx.x * (KDIM * CDIM);
    const int rql = lane >> 2, cql = (lane & 3) * 2;
    #pragma unroll
    for (int i = 0; i < 4; i++) {
        int row = wm * 64 + i * 16 + rql;
        #pragma unroll
        for (int j = 0; j < 4; j++) {
            int col = wn * 32 + j * 8 + cql;
            *(float2*)(base + row * CDIM + col)       = make_float2(d[i][j][0], d[i][j][1]);
            *(float2*)(base + (row + 8) * CDIM + col) = make_float2(d[i][j][2], d[i][j][3]);
        }
    }
}

// =====================================================================
// Reduce: xs[k][c] = exp(-evals[k]*t) * sum_b part[b][k][c]
// Output in B-fragment layout (tf32 bits).
// =====================================================================
__global__ void reduce_kernel(const float* __restrict__ evals,
                              const float* __restrict__ dt)
{
    int idx = blockIdx.x * 256 + threadIdx.x;
    float s0 = 0.f, s1 = 0.f, s2 = 0.f, s3 = 0.f;
    int b = 0;
    for (; b + 4 <= P1_BLOCKS; b += 4) {
        s0 += g_part[(size_t)(b + 0) * (KDIM * CDIM) + idx];
        s1 += g_part[(size_t)(b + 1) * (KDIM * CDIM) + idx];
        s2 += g_part[(size_t)(b + 2) * (KDIM * CDIM) + idx];
        s3 += g_part[(size_t)(b + 3) * (KDIM * CDIM) + idx];
    }
    for (; b < P1_BLOCKS; b++) s0 += g_part[(size_t)b * (KDIM * CDIM) + idx];
    float s = (s0 + s1) + (s2 + s3);

    int k = idx >> 7, c = idx & 127;
    float t = fmaxf(dt[0], 1e-8f);
    float v = expf(-evals[k] * t) * s;

    int k8 = k >> 3, kL = k & 7, ct = c >> 3, cL = c & 7;
    uint32_t addr = (uint32_t)(((k8 * 16 + ct) * 32 + cL * 4 + (kL & 3)) * 2 + (kL >> 2));
    g_xsB[addr] = __uint_as_float(tf32r(v));
}

// =====================================================================
// Phase 2: out = E @ xs.  M-tile 128, 256 thr = 8 warps (2m x 4n).
// 32-k chunks: B frag cp.async (contiguous), A raw cp.async + repack.
// 66 KB smem -> 2 CTAs/SM.
// =====================================================================
__global__ void __launch_bounds__(256, 2)
phase2_kernel(const float* __restrict__ E, float* __restrict__ out, int N)
{
    extern __shared__ uint32_t sm[];
    const uint32_t sbase = smem_u32(sm);

    const int tid = threadIdx.x;
    const int warp = tid >> 5, lane = tid & 31;
    const int wm = warp >> 2;        // 0..1
    const int wn = warp & 3;         // 0..3
    const int m0 = blockIdx.x * 128;

    // cp.async one 32-k chunk: B frag (contiguous) + A raw (stride 36)
    auto copy_chunk = [&](int kc) {
        const int bbuf = kc & 1;
        #pragma unroll
        for (int t = 0; t < 4; t++) {        // B: 1024 x 16B
            int idx = tid + t * 256;
            cpa16(sbase + (uint32_t)(bbuf * P2_BST + idx * 4) * 4,
                  (const uint32_t*)g_xsB + kc * P2_BST + idx * 4);
        }
        #pragma unroll
        for (int t = 0; t < 4; t++) {        // A: 128 rows x 8 float4
            int idx = tid + t * 256;
            int r = idx >> 3, j = idx & 7;
            int row = m0 + r; if (row >= N) row = N - 1;
            cpa16(sbase + (uint32_t)(P2_ARAW + r * P2_ARS + j * 4) * 4,
                  E + (size_t)row * KDIM + kc * 32 + j * 4);
        }
    };

    copy_chunk(0);
    CP_COMMIT();

    float d[4][4][4];
    #pragma unroll
    for (int i = 0; i < 4; i++)
        #pragma unroll
        for (int j = 0; j < 4; j++)
            #pragma unroll
            for (int q = 0; q < 4; q++) d[i][j][q] = 0.f;

    const float*    Araw = (const float*)(sm + P2_ARAW);
    uint32_t*       Afrg = sm + P2_AFRG;

    for (int kc = 0; kc < 8; kc++) {
        CP_WAIT0();
        __syncthreads();                     // raw+B ready; prior MMA done (frag free)

        // repack A raw -> frag (conflict-free gather, STS.128)
        #pragma unroll
        for (int s = 0; s < 4; s++) {
            int sid = tid + s * 256;         // (k8, mt, l)
            int k8 = sid >> 8, mt = (sid >> 5) & 7, l = sid & 31;
            uint32_t w[4];
            #pragma unroll
            for (int q = 0; q < 4; q++) {
                int row = mt * 16 + (l >> 2) + 8 * (q & 1);
                int col = k8 * 8 + (l & 3) + 4 * (q >> 1);
                w[q] = tf32r(Araw[row * P2_ARS + col]);
            }
            *(uint4*)(Afrg + ((k8 * 8 + mt) * 32 + l) * 4) =
                make_uint4(w[0], w[1], w[2], w[3]);
        }
        __syncthreads();                     // frag ready; raw free

        if (kc + 1 < 8) copy_chunk(kc + 1);
        CP_COMMIT();

        const uint32_t* Bf = sm + (kc & 1) * P2_BST;
        #pragma unroll
        for (int k8l = 0; k8l < 4; k8l++) {
            uint32_t a[4][4], b[4][2];
            #pragma unroll
            for (int i = 0; i < 4; i++) {
                uint4 av = *(const uint4*)(Afrg + ((k8l * 8 + wm * 4 + i) * 32 + lane) * 4);
                a[i][0] = av.x; a[i][1] = av.y; a[i][2] = av.z; a[i][3] = av.w;
            }
            #pragma unroll
            for (int j = 0; j < 4; j++) {
                uint2 bv = *(const uint2*)(Bf + ((k8l * 16 + wn * 4 + j) * 32 + lane) * 2);
                b[j][0] = bv.x; b[j][1] = bv.y;
            }
            #pragma unroll
            for (int i = 0; i < 4; i++)
                #pragma unroll
                for (int j = 0; j < 4; j++)
                    mma8(d[i][j], a[i], b[j]);
        }
    }

    const int rql = lane >> 2, cql = (lane & 3) * 2;
    #pragma unroll
    for (int i = 0; i < 4; i++) {
        int row = m0 + wm * 64 + i * 16 + rql;
        #pragma unroll
        for (int j = 0; j < 4; j++) {
            int col = wn * 32 + j * 8 + cql;
            if (row < N)
                *(float2*)(out + (size_t)row * CDIM + col) = make_float2(d[i][j][0], d[i][j][1]);
            if (row + 8 < N)
                *(float2*)(out + (size_t)(row + 8) * CDIM + col) = make_float2(d[i][j][2], d[i][j][3]);
        }
    }
}

// =====================================================================
extern "C" void kernel_launch(void* const* d_in, const int* in_sizes, int n_in,
                              void* d_out, int out_size)
{
    const float* evals = nullptr;
    const float* dt = nullptr;
    long big_a = -1, big_b = -1; int ia = -1, ib = -1;
    for (int i = 0; i < n_in; i++) {
        long sz = in_sizes[i];
        if (sz == 1)         dt = (const float*)d_in[i];
        else if (sz == KDIM) evals = (const float*)d_in[i];
        else {
            if (sz > big_a) { big_b = big_a; ib = ia; big_a = sz; ia = i; }
            else if (sz > big_b) { big_b = sz; ib = i; }
        }
    }
    const float* evecs = (const float*)d_in[ia];   // N*K (largest)
    const float* x     = (const float*)d_in[ib];   // N*C
    const int N = (int)(big_b / CDIM);

    static int cfg = 0;
    if (!cfg) {
        cudaFuncSetAttribute(phase1_kernel, cudaFuncAttributeMaxDynamicSharedMemorySize, P1_SMEM);
        cudaFuncSetAttribute(phase2_kernel, cudaFuncAttributeMaxDynamicSharedMemorySize, P2_SMEM);
        cfg = 1;
    }

    const int chunk = (N + P1_BLOCKS - 1) / P1_BLOCKS;
    phase1_kernel<<<P1_BLOCKS, 512, P1_SMEM>>>(evecs, x, N, chunk);
    reduce_kernel<<<(KDIM * CDIM) / 256, 256>>>(evals, dt);
    phase2_kernel<<<(N + 127) / 128, 256, P2_SMEM>>>(evecs, (float*)d_out, N);
}

// round 8
// speedup vs baseline: 1.2820x; 1.0551x over previous
#include <cuda_runtime.h>
#include <cuda_bf16.h>
#include <cstdint>
#include <math.h>

#define KDIM 256
#define CDIM 128
#define P1_BLOCKS 148

__device__ float g_part[P1_BLOCKS * KDIM * CDIM];   // phase1 partials (fp32)
__device__ float g_xsB[KDIM * CDIM];                // spectrum, B-fragment layout (tf32 bits)

// ---------------- helpers (sm_80-level PTX only) ----------------
__device__ __forceinline__ uint32_t tf32r(float x) {
    uint32_t u; asm("cvt.rna.tf32.f32 %0, %1;" : "=r"(u) : "f"(x)); return u;
}
__device__ __forceinline__ void mma8(float* d, const uint32_t* a, const uint32_t* b) {
    asm volatile(
        "mma.sync.aligned.m16n8k8.row.col.f32.tf32.tf32.f32 "
        "{%0,%1,%2,%3}, {%4,%5,%6,%7}, {%8,%9}, {%0,%1,%2,%3};"
        : "+f"(d[0]), "+f"(d[1]), "+f"(d[2]), "+f"(d[3])
        : "r"(a[0]), "r"(a[1]), "r"(a[2]), "r"(a[3]), "r"(b[0]), "r"(b[1]));
}
__device__ __forceinline__ uint32_t smem_u32(const void* p) {
    uint32_t a;
    asm("{ .reg .u64 t; cvta.to.shared.u64 t, %1; cvt.u32.u64 %0, t; }" : "=r"(a) : "l"(p));
    return a;
}
__device__ __forceinline__ void cpa16(uint32_t dst, const void* src) {
    asm volatile("cp.async.ca.shared.global [%0], [%1], 16;"
                 :: "r"(dst), "l"(src) : "memory");
}
#define CP_COMMIT() asm volatile("cp.async.commit_group;" ::: "memory")
#define CP_WAIT0()  asm volatile("cp.async.wait_group 0;" ::: "memory")

// Fragment maps (m16n8k8 tf32):
//  A: reg q, lane l -> mL = (l>>2)+8*(q&1), kL = (l&3)+4*(q>>1)
//  B: reg q, lane l -> nL = l>>2,           kL = (l&3)+4*q
//  D: c0,c1 -> row=l/4, col=2*(l%4)+{0,1}; c2,c3 -> row+8

// ---- Phase1 v2: M-split CTAs, 16-node chunks ----
// A frag: [2 k8][8 mt][32 lane][4 reg], mt stride 132, k8 stride 1056
// B frag: [2 k8][16 ct][66],            k8 stride 1056
#define P1_K8S  1056
#define P1_FBUF 2112
#define P1_SMEM (4 * P1_FBUF * 4)      // 33792 B -> 2 CTAs/SM

// ---- Phase2 geometry: 32-k chunks, 8 chunks (R7, proven) ----
#define P2_BST   4096
#define P2_ARAW  8192
#define P2_ARS   36
#define P2_AFRG  (P2_ARAW + 128 * P2_ARS)
#define P2_TOT   (P2_AFRG + 4096)
#define P2_SMEM  (P2_TOT * 4)          // 67584 B -> 2 CTAs/SM

// =====================================================================
// Phase 1 v2: partial[range][h*128 + m][c] = evecs_half^T @ x.
// Grid (148, 2). 256 thr = 8 warps (2m x 4n), warp tile 64x32.
// 16-node chunks, double-buffered regs + frag smem, 2 CTAs/SM.
// =====================================================================
__global__ void __launch_bounds__(256, 2)
phase1_kernel(const float* __restrict__ E, const float* __restrict__ X,
              int N, int chunk)
{
    extern __shared__ uint32_t sm[];
    uint32_t* Af = sm;                   // 2 x P1_FBUF
    uint32_t* Bf = sm + 2 * P1_FBUF;     // 2 x P1_FBUF

    const int tid = threadIdx.x;
    const int warp = tid >> 5, lane = tid & 31;
    const int wm = warp >> 2;            // 0..1 -> m0 = wm*64
    const int wn = warp & 3;             // 0..3 -> n0 = wn*32
    const int h = blockIdx.y;            // eigen half

    float d[4][4][4];
    #pragma unroll
    for (int i = 0; i < 4; i++)
        #pragma unroll
        for (int j = 0; j < 4; j++)
            #pragma unroll
            for (int q = 0; q < 4; q++) d[i][j][q] = 0.f;

    const int nb = blockIdx.x * chunk;
    const int ne = min(N, nb + chunk);
    const int niter = (ne - nb + 15) >> 4;

    float4 curA[2], curB[2];

    auto loadc = [&](int s0, float4* A2, float4* B2) {
        #pragma unroll
        for (int it = 0; it < 2; it++) {
            int fid = tid + it * 256;        // 0..511
            int r = fid >> 5, j = fid & 31;  // node-in-chunk, f4 index
            int node = s0 + r;
            A2[it] = (node < ne)
                ? *(const float4*)(E + (size_t)node * KDIM + h * 128 + 4 * j)
                : make_float4(0.f, 0.f, 0.f, 0.f);
            B2[it] = (node < ne)
                ? *(const float4*)(X + (size_t)node * CDIM + 4 * j)
                : make_float4(0.f, 0.f, 0.f, 0.f);
        }
    };

    loadc(nb, curA, curB);

    for (int itn = 0; itn < niter; itn++) {
        const int buf = itn & 1;
        float4 nxtA[2], nxtB[2];
        if (itn + 1 < niter) loadc(nb + (itn + 1) * 16, nxtA, nxtB);

        uint32_t* Ab = Af + buf * P1_FBUF;
        uint32_t* Bb = Bf + buf * P1_FBUF;

        #pragma unroll
        for (int it = 0; it < 2; it++) {
            int fid = tid + it * 256;
            int r = fid >> 5, j = fid & 31;
            int k8 = r >> 3;
            // A scatter: m = 4j+q (0..127)
            uint32_t abase = (uint32_t)(k8 * P1_K8S + (j >> 2) * 132
                           + 64 * (j & 1) + 4 * (r & 3)
                           + ((j >> 1) & 1) + 2 * ((r >> 2) & 1));
            const float* vA = (const float*)&curA[it];
            #pragma unroll
            for (int q = 0; q < 4; q++)
                Ab[abase + 16u * q] = tf32r(vA[q]);
            // B scatter: c = 4j+q
            uint32_t bbase = (uint32_t)(k8 * P1_K8S + (j >> 1) * 66
                           + 32 * (j & 1) + 2 * (r & 3) + ((r >> 2) & 1));
            const float* vB = (const float*)&curB[it];
            #pragma unroll
            for (int q = 0; q < 4; q++)
                Bb[bbase + 8u * q] = tf32r(vB[q]);
        }
        __syncthreads();

        #pragma unroll
        for (int k8 = 0; k8 < 2; k8++) {
            uint32_t a[4][4], b[4][2];
            #pragma unroll
            for (int i = 0; i < 4; i++) {
                uint4 av = *(const uint4*)(Ab + k8 * P1_K8S + (wm * 4 + i) * 132 + lane * 4);
                a[i][0] = av.x; a[i][1] = av.y; a[i][2] = av.z; a[i][3] = av.w;
            }
            #pragma unroll
            for (int j = 0; j < 4; j++) {
                uint2 bv = *(const uint2*)(Bb + k8 * P1_K8S + (wn * 4 + j) * 66 + lane * 2);
                b[j][0] = bv.x; b[j][1] = bv.y;
            }
            #pragma unroll
            for (int i = 0; i < 4; i++)
                #pragma unroll
                for (int j = 0; j < 4; j++)
                    mma8(d[i][j], a[i], b[j]);
        }
        __syncthreads();

        curA[0] = nxtA[0]; curA[1] = nxtA[1];
        curB[0] = nxtB[0]; curB[1] = nxtB[1];
    }

    float* base = g_part + (size_t)blockIdx.x * (KDIM * CDIM);
    const int rql = lane >> 2, cql = (lane & 3) * 2;
    #pragma unroll
    for (int i = 0; i < 4; i++) {
        int row = h * 128 + wm * 64 + i * 16 + rql;
        #pragma unroll
        for (int j = 0; j < 4; j++) {
            int col = wn * 32 + j * 8 + cql;
            *(float2*)(base + row * CDIM + col)       = make_float2(d[i][j][0], d[i][j][1]);
            *(float2*)(base + (row + 8) * CDIM + col) = make_float2(d[i][j][2], d[i][j][3]);
        }
    }
}

// =====================================================================
// Reduce: xs[k][c] = exp(-evals[k]*t) * sum_b part[b][k][c]
// Output in B-fragment layout (tf32 bits).
// =====================================================================
__global__ void reduce_kernel(const float* __restrict__ evals,
                              const float* __restrict__ dt)
{
    int idx = blockIdx.x * 256 + threadIdx.x;
    float s0 = 0.f, s1 = 0.f, s2 = 0.f, s3 = 0.f;
    int b = 0;
    for (; b + 4 <= P1_BLOCKS; b += 4) {
        s0 += g_part[(size_t)(b + 0) * (KDIM * CDIM) + idx];
        s1 += g_part[(size_t)(b + 1) * (KDIM * CDIM) + idx];
        s2 += g_part[(size_t)(b + 2) * (KDIM * CDIM) + idx];
        s3 += g_part[(size_t)(b + 3) * (KDIM * CDIM) + idx];
    }
    for (; b < P1_BLOCKS; b++) s0 += g_part[(size_t)b * (KDIM * CDIM) + idx];
    float s = (s0 + s1) + (s2 + s3);

    int k = idx >> 7, c = idx & 127;
    float t = fmaxf(dt[0], 1e-8f);
    float v = expf(-evals[k] * t) * s;

    int k8 = k >> 3, kL = k & 7, ct = c >> 3, cL = c & 7;
    uint32_t addr = (uint32_t)(((k8 * 16 + ct) * 32 + cL * 4 + (kL & 3)) * 2 + (kL >> 2));
    g_xsB[addr] = __uint_as_float(tf32r(v));
}

// =====================================================================
// Phase 2 (R7, proven): out = E @ xs. M-tile 128, 256 thr, 8 warps,
// 32-k chunks, B frag cp.async + A raw cp.async + repack, 2 CTAs/SM.
// =====================================================================
__global__ void __launch_bounds__(256, 2)
phase2_kernel(const float* __restrict__ E, float* __restrict__ out, int N)
{
    extern __shared__ uint32_t sm[];
    const uint32_t sbase = smem_u32(sm);

    const int tid = threadIdx.x;
    const int warp = tid >> 5, lane = tid & 31;
    const int wm = warp >> 2;
    const int wn = warp & 3;
    const int m0 = blockIdx.x * 128;

    auto copy_chunk = [&](int kc) {
        const int bbuf = kc & 1;
        #pragma unroll
        for (int t = 0; t < 4; t++) {
            int idx = tid + t * 256;
            cpa16(sbase + (uint32_t)(bbuf * P2_BST + idx * 4) * 4,
                  (const uint32_t*)g_xsB + kc * P2_BST + idx * 4);
        }
        #pragma unroll
        for (int t = 0; t < 4; t++) {
            int idx = tid + t * 256;
            int r = idx >> 3, j = idx & 7;
            int row = m0 + r; if (row >= N) row = N - 1;
            cpa16(sbase + (uint32_t)(P2_ARAW + r * P2_ARS + j * 4) * 4,
                  E + (size_t)row * KDIM + kc * 32 + j * 4);
        }
    };

    copy_chunk(0);
    CP_COMMIT();

    float d[4][4][4];
    #pragma unroll
    for (int i = 0; i < 4; i++)
        #pragma unroll
        for (int j = 0; j < 4; j++)
            #pragma unroll
            for (int q = 0; q < 4; q++) d[i][j][q] = 0.f;

    const float* Araw = (const float*)(sm + P2_ARAW);
    uint32_t*    Afrg = sm + P2_AFRG;

    for (int kc = 0; kc < 8; kc++) {
        CP_WAIT0();
        __syncthreads();

        #pragma unroll
        for (int s = 0; s < 4; s++) {
            int sid = tid + s * 256;
            int k8 = sid >> 8, mt = (sid >> 5) & 7, l = sid & 31;
            uint32_t w[4];
            #pragma unroll
            for (int q = 0; q < 4; q++) {
                int row = mt * 16 + (l >> 2) + 8 * (q & 1);
                int col = k8 * 8 + (l & 3) + 4 * (q >> 1);
                w[q] = tf32r(Araw[row * P2_ARS + col]);
            }
            *(uint4*)(Afrg + ((k8 * 8 + mt) * 32 + l) * 4) =
                make_uint4(w[0], w[1], w[2], w[3]);
        }
        __syncthreads();

        if (kc + 1 < 8) copy_chunk(kc + 1);
        CP_COMMIT();

        const uint32_t* Bf = sm + (kc & 1) * P2_BST;
        #pragma unroll
        for (int k8l = 0; k8l < 4; k8l++) {
            uint32_t a[4][4], b[4][2];
            #pragma unroll
            for (int i = 0; i < 4; i++) {
                uint4 av = *(const uint4*)(Afrg + ((k8l * 8 + wm * 4 + i) * 32 + lane) * 4);
                a[i][0] = av.x; a[i][1] = av.y; a[i][2] = av.z; a[i][3] = av.w;
            }
            #pragma unroll
            for (int j = 0; j < 4; j++) {
                uint2 bv = *(const uint2*)(Bf + ((k8l * 16 + wn * 4 + j) * 32 + lane) * 2);
                b[j][0] = bv.x; b[j][1] = bv.y;
            }
            #pragma unroll
            for (int i = 0; i < 4; i++)
                #pragma unroll
                for (int j = 0; j < 4; j++)
                    mma8(d[i][j], a[i], b[j]);
        }
    }

    const int rql = lane >> 2, cql = (lane & 3) * 2;
    #pragma unroll
    for (int i = 0; i < 4; i++) {
        int row = m0 + wm * 64 + i * 16 + rql;
        #pragma unroll
        for (int j = 0; j < 4; j++) {
            int col = wn * 32 + j * 8 + cql;
            if (row < N)
                *(float2*)(out + (size_t)row * CDIM + col) = make_float2(d[i][j][0], d[i][j][1]);
            if (row + 8 < N)
                *(float2*)(out + (size_t)(row + 8) * CDIM + col) = make_float2(d[i][j][2], d[i][j][3]);
        }
    }
}

// =====================================================================
extern "C" void kernel_launch(void* const* d_in, const int* in_sizes, int n_in,
                              void* d_out, int out_size)
{
    const float* evals = nullptr;
    const float* dt = nullptr;
    long big_a = -1, big_b = -1; int ia = -1, ib = -1;
    for (int i = 0; i < n_in; i++) {
        long sz = in_sizes[i];
        if (sz == 1)         dt = (const float*)d_in[i];
        else if (sz == KDIM) evals = (const float*)d_in[i];
        else {
            if (sz > big_a) { big_b = big_a; ib = ia; big_a = sz; ia = i; }
            else if (sz > big_b) { big_b = sz; ib = i; }
        }
    }
    const float* evecs = (const float*)d_in[ia];   // N*K (largest)
    const float* x     = (const float*)d_in[ib];   // N*C
    const int N = (int)(big_b / CDIM);

    static int cfg = 0;
    if (!cfg) {
        cudaFuncSetAttribute(phase1_kernel, cudaFuncAttributeMaxDynamicSharedMemorySize, P1_SMEM);
        cudaFuncSetAttribute(phase2_kernel, cudaFuncAttributeMaxDynamicSharedMemorySize, P2_SMEM);
        cfg = 1;
    }

    const int chunk = (N + P1_BLOCKS - 1) / P1_BLOCKS;
    phase1_kernel<<<dim3(P1_BLOCKS, 2), 256, P1_SMEM>>>(evecs, x, N, chunk);
    reduce_kernel<<<(KDIM * CDIM) / 256, 256>>>(evals, dt);
    phase2_kernel<<<(N + 127) / 128, 256, P2_SMEM>>>(evecs, (float*)d_out, N);
}